// round 15
// baseline (speedup 1.0000x reference)
#include <cuda_runtime.h>
#include <math.h>

#define BATCH 16
#define NHEAD 8
#define HDIM 128
#define BSZ 16
#define SEQL 4096
#define MAXB 384
#define HID 1024
#define NTOK 4097          // 16 sink + 4064 window + 16 partial block + 1 new
#define NSPLIT 57          // ceil(4097 / 72); no empty splits
#define TPS 72             // MULTIPLE OF 8 and of STAGE
#define NTOKP 4104         // row pitch (mult of 8, 16B-aligned)
#define NGRP 8             // reduce stage-A groups
#define KSPLIT 16
#define GEMM_KB 64
#define STAGE 24           // tokens staged per cp.async group (72 = 3*24)
#define SCALE 0.08838834764831845f
#define MSHIFT 10.0f       // fixed softmax shift (scores bounded << 80)

typedef unsigned long long u64;

// ---------------- scratch (device globals: no allocation allowed) ----------
__device__ float g_part_acc[BATCH * NSPLIT * NHEAD * HDIM]; // 3.6 MB
__device__ float g_part_l[BATCH * NSPLIT * NHEAD];
__device__ float g_acc2[BATCH * NHEAD * NGRP * HDIM];
__device__ float g_l2[BATCH * NHEAD * NGRP];
__device__ float g_scores[BATCH * NHEAD * NTOKP];           // weights
__device__ float g_attn[BATCH * HID];
__device__ float g_gemm_part[KSPLIT * BATCH * HID];
__device__ float g_ropeT[SEQL * 128];   // per pos: [0:64) cos, [64:128) sin
__device__ int2  g_rowpos[BATCH * NTOK];

__device__ __forceinline__ float4 ldg4(const float* p) {
    return *reinterpret_cast<const float4*>(p);
}
__device__ __forceinline__ ulonglong2 ldg4u(const float* p) {
    return *reinterpret_cast<const ulonglong2*>(p);
}
__device__ __forceinline__ u64 pk2(float a, float b) {
    u64 r; asm("mov.b64 %0, {%1, %2};" : "=l"(r) : "f"(a), "f"(b)); return r;
}
__device__ __forceinline__ u64 mul2(u64 a, u64 b) {
    u64 r; asm("mul.rn.f32x2 %0, %1, %2;" : "=l"(r) : "l"(a), "l"(b)); return r;
}
__device__ __forceinline__ u64 fma2(u64 a, u64 b, u64 c) {
    u64 r; asm("fma.rn.f32x2 %0, %1, %2, %3;" : "=l"(r) : "l"(a), "l"(b), "l"(c)); return r;
}
__device__ __forceinline__ float hadd2(u64 v) {
    float a, b; asm("mov.b64 {%0, %1}, %2;" : "=f"(a), "=f"(b) : "l"(v));
    return a + b;
}
__device__ __forceinline__ void cp_async16(void* smem, const void* gmem) {
    unsigned sa = (unsigned)__cvta_generic_to_shared(smem);
    asm volatile("cp.async.ca.shared.global [%0], [%1], 16;\n"
                 :: "r"(sa), "l"(gmem) : "memory");
}
__device__ __forceinline__ void cp_async_commit() {
    asm volatile("cp.async.commit_group;\n" ::: "memory");
}
__device__ __forceinline__ void cp_async_wait_all() {
    asm volatile("cp.async.wait_group 0;\n" ::: "memory");
}

// invf[f] = 10000^(-f/64) = r^f, r hardcoded, fp64 binary exponentiation.
__device__ __forceinline__ float invf_of(int f) {
    double base = 0.86596432336006535;   // 10000^(-1/64)
    double p = 1.0;
    int e = f;
    while (e) {
        if (e & 1) p *= base;
        base *= base;
        e >>= 1;
    }
    return (float)p;
}

// ---------------------------------------------------------------------------
// Setup (single kernel): blocks 0..2047 build the RoPE table; blocks
// 2048..2063 build rowpos for batch (blockIdx - 2048). block = 128.
// ---------------------------------------------------------------------------
__global__ __launch_bounds__(128) void setup_kernel(
    const int* __restrict__ bt, const int* __restrict__ sl)
{
    if (blockIdx.x < 2048) {
        const int idx = blockIdx.x * 128 + threadIdx.x;  // p*64 + f
        const int p = idx >> 6;
        const int f = idx & 63;
        float sv, cv;
        sincosf((float)p * invf_of(f), &sv, &cv);
        g_ropeT[p * 128 + f] = cv;
        g_ropeT[p * 128 + 64 + f] = sv;
        return;
    }

    const int b = blockIdx.x - 2048;
    const int num_past = sl[b] - 1;
    const int mblk = num_past >> 4;
    const int rem = num_past & 15;
    const int* btb = bt + b * MAXB;

    for (int t = threadIdx.x; t < NTOK; t += 128) {
        int row, p;
        if (t < 16) {
            row = btb[0] * BSZ + t;
            p = t;
        } else if (t < 4080) {
            int blk = btb[mblk - 254 + ((t - 16) >> 4)];
            row = blk * BSZ + ((t - 16) & 15);
            p = t + 15 - rem;
        } else if (t < 4096) {
            int off = t - 4080;
            row = (off < rem) ? (btb[mblk] * BSZ + off) : -1;
            p = t - 1 - rem;
        } else {
            row = -2;
            p = 4095;
        }
        g_rowpos[b * NTOK + t] = make_int2(row, p);
    }
}

// ---------------------------------------------------------------------------
// Kernel 1: weights w[b][h][t] = exp(dot(rope q, rope K_t)*SCALE - MSHIFT).
// grid = (NSPLIT, BATCH), block = 256 (warp == head).
// cp.async double-buffered 24-token rope staging (3 syncs/split), packed
// f32x2 math, transposed butterfly: lane A finalizes token g + half*4 + (A&3).
// ---------------------------------------------------------------------------
__global__ __launch_bounds__(256) void score_kernel(
    const float* __restrict__ q, const float* __restrict__ k,
    const float* __restrict__ kc)
{
    __shared__ float sbuf[2][STAGE][128];
    __shared__ int srow[2][STAGE];

    const int b = blockIdx.y;
    const int s = blockIdx.x;
    const int tid = threadIdx.x;
    const int h = tid >> 5;
    const int lane = tid & 31;
    const int A = lane & 15;
    const int half = lane >> 4;
    const int d4 = A * 4;
    const int tokoff = half * 4 + (A & 3);   // within an 8-token subgroup

    const int tstart = s * TPS;
    const int tend = min(tstart + TPS, NTOK);

    // --- rope q at pos 4095 (owned dims, scalar once, then pack) ---
    const int hb = h * HDIM;
    float4 qx4 = ldg4(q + b * HID + hb + d4);
    float4 qy4 = ldg4(q + b * HID + hb + 64 + d4);
    float4 c04 = ldg4(g_ropeT + 4095 * 128 + d4);
    float4 s04 = ldg4(g_ropeT + 4095 * 128 + 64 + d4);
    float ql[4], qh[4];
    ql[0] = qx4.x * c04.x - qy4.x * s04.x;
    ql[1] = qx4.y * c04.y - qy4.y * s04.y;
    ql[2] = qx4.z * c04.z - qy4.z * s04.z;
    ql[3] = qx4.w * c04.w - qy4.w * s04.w;
    qh[0] = qy4.x * c04.x + qx4.x * s04.x;
    qh[1] = qy4.y * c04.y + qx4.y * s04.y;
    qh[2] = qy4.z * c04.z + qx4.z * s04.z;
    qh[3] = qy4.w * c04.w + qx4.w * s04.w;
    const u64 qlo0 = pk2(ql[0], ql[1]), qlo1 = pk2(ql[2], ql[3]);
    const u64 qhi0 = pk2(qh[0], qh[1]), qhi1 = pk2(qh[2], qh[3]);
    const u64 nqlo0 = pk2(-ql[0], -ql[1]), nqlo1 = pk2(-ql[2], -ql[3]);

    // --- stage chunk at t0s into buffer buf (cp.async, STAGE*32 float4s) ---
    #define STAGE_CHUNK(t0s, buf)                                          \
    do {                                                                   \
        _Pragma("unroll")                                                  \
        for (int e = tid; e < STAGE * 32; e += 256) {                      \
            const int ti = e >> 5;                                         \
            const int c = e & 31;                                          \
            const int t = (t0s) + ti;                                      \
            if (t < tend) {                                                \
                int2 rp = g_rowpos[b * NTOK + t];                          \
                cp_async16(&sbuf[buf][ti][c * 4],                          \
                           g_ropeT + rp.y * 128 + c * 4);                  \
                if (c == 0) srow[buf][ti] = rp.x;                          \
            } else if (c == 0) {                                           \
                srow[buf][ti] = -1;                                        \
            }                                                              \
        }                                                                  \
        cp_async_commit();                                                 \
    } while (0)

    STAGE_CHUNK(tstart, 0);

    const float* kq = k + b * HID;
    const long sbase = (long)(b * NHEAD + h) * NTOKP;
    float lsum = 0.0f;
    int cur = 0;

    for (int t0 = tstart; t0 < tend; t0 += STAGE) {
        cp_async_wait_all();
        __syncthreads();
        if (t0 + STAGE < tend)
            STAGE_CHUNK(t0 + STAGE, cur ^ 1);

        // ---- three 8-token subgroups ----
#pragma unroll
        for (int g = 0; g < STAGE; g += 8) {
            if (t0 + g >= tend) break;
            float dot[4];
#pragma unroll
            for (int sub = 0; sub < 4; sub++) {
                const int ti = g + half * 4 + sub;
                const int row = srow[cur][ti];
                const float* kp = (row == -2) ? kq
                                 : kc + (long)max(row, 0) * HID;
                ulonglong2 kx = ldg4u(kp + hb + d4);
                ulonglong2 ky = ldg4u(kp + hb + 64 + d4);
                ulonglong2 cc = *reinterpret_cast<const ulonglong2*>(&sbuf[cur][ti][d4]);
                ulonglong2 ss = *reinterpret_cast<const ulonglong2*>(&sbuf[cur][ti][64 + d4]);
                u64 acc = 0ULL;
                u64 P0 = fma2(qlo0, kx.x, mul2(qhi0, ky.x));
                u64 M0 = fma2(qhi0, kx.x, mul2(nqlo0, ky.x));
                acc = fma2(cc.x, P0, acc);
                acc = fma2(ss.x, M0, acc);
                u64 P1 = fma2(qlo1, kx.y, mul2(qhi1, ky.y));
                u64 M1 = fma2(qhi1, kx.y, mul2(nqlo1, ky.y));
                acc = fma2(cc.y, P1, acc);
                acc = fma2(ss.y, M1, acc);
                dot[sub] = hadd2(acc);
            }

            // ---- transposed butterfly over the 16-lane half ----
            float k0 = ((A & 1) == 0) ? dot[0] : dot[1];
            float s0 = ((A & 1) == 0) ? dot[1] : dot[0];
            float v01 = k0 + __shfl_xor_sync(0xffffffffu, s0, 1);
            float k1 = ((A & 1) == 0) ? dot[2] : dot[3];
            float s1 = ((A & 1) == 0) ? dot[3] : dot[2];
            float v23 = k1 + __shfl_xor_sync(0xffffffffu, s1, 1);
            float k2 = ((A & 2) == 0) ? v01 : v23;
            float s2 = ((A & 2) == 0) ? v23 : v01;
            float vv = k2 + __shfl_xor_sync(0xffffffffu, s2, 2);
            vv += __shfl_xor_sync(0xffffffffu, vv, 4);
            vv += __shfl_xor_sync(0xffffffffu, vv, 8);

            const int t_mine = t0 + g + tokoff;
            const bool okm = (t_mine < tend) && (srow[cur][g + tokoff] != -1);
            float w = okm ? __expf(fmaf(vv, SCALE, -MSHIFT)) : 0.0f;
            if (A < 4) {
                g_scores[sbase + t_mine] = w;
                lsum += w;
            }
        }
        cur ^= 1;
    }
    #undef STAGE_CHUNK

    // warp-wide lsum (non-storing lanes hold 0)
#pragma unroll
    for (int o = 16; o > 0; o >>= 1)
        lsum += __shfl_xor_sync(0xffffffffu, lsum, o);
    if (lane == 0)
        g_part_l[(b * NSPLIT + s) * NHEAD + h] = lsum;
}

// ---------------------------------------------------------------------------
// Kernel 2: partials acc = sum_t w_t * V_t. Pure streaming (proven body).
// grid = (NSPLIT, BATCH), block = 256 (warp == head). No smem, no syncs.
// ---------------------------------------------------------------------------
__global__ __launch_bounds__(256) void wv_kernel(
    const float* __restrict__ v, const float* __restrict__ vc)
{
    const int b = blockIdx.y;
    const int s = blockIdx.x;
    const int tid = threadIdx.x;
    const int h = tid >> 5;
    const int lane = tid & 31;
    const int hoff = h * HDIM + lane * 4;

    const int tstart = s * TPS;
    const int tend = min(tstart + TPS, NTOK);
    const float* vq = v + b * HID;
    const float* wrow = g_scores + (long)(b * NHEAD + h) * NTOKP;

    float acc[4] = {0.f, 0.f, 0.f, 0.f};

    for (int t0 = tstart; t0 < tend; t0 += 8) {
        float4 w0 = ldg4(wrow + t0);
        float4 w1 = ldg4(wrow + t0 + 4);
        float wv_[8] = {w0.x, w0.y, w0.z, w0.w, w1.x, w1.y, w1.z, w1.w};
        float4 vv[8];
#pragma unroll
        for (int i = 0; i < 8; i++) {
            int t = min(t0 + i, NTOK - 1);
            int row = g_rowpos[b * NTOK + t].x;
            const float* vp = (row == -2) ? vq : vc + (long)max(row, 0) * HID;
            vv[i] = ldg4(vp + hoff);
        }
#pragma unroll
        for (int j = 0; j < 4; j++) {
            float x = acc[j];
#pragma unroll
            for (int i = 0; i < 8; i++)
                x = fmaf(wv_[i], (&vv[i].x)[j], x);
            acc[j] = x;
        }
    }

    float* pa = g_part_acc +
        (long)((b * NSPLIT + s) * NHEAD + h) * HDIM + lane * 4;
    pa[0] = acc[0]; pa[1] = acc[1]; pa[2] = acc[2]; pa[3] = acc[3];
}

// ---------------------------------------------------------------------------
// Reduce stage A: sum 8 splits per group (group 7 = split 56 only).
// grid = (NGRP, 128 bh), block = 128.
// ---------------------------------------------------------------------------
__global__ __launch_bounds__(128) void reduceA_kernel()
{
    const int g = blockIdx.x;
    const int bh = blockIdx.y;
    const int b = bh >> 3;
    const int h = bh & 7;
    const int d = threadIdx.x;
    const int s0 = g * 8;

    const float* base =
        g_part_acc + (long)((b * NSPLIT + s0) * NHEAD + h) * HDIM + d;
    float sum;
    if (g < NGRP - 1) {
        sum = 0.0f;
#pragma unroll
        for (int i = 0; i < 8; i++)
            sum += base[(long)i * NHEAD * HDIM];
    } else {
        sum = base[0];   // split 56 only
    }
    g_acc2[((long)bh * NGRP + g) * HDIM + d] = sum;

    if (d == 0) {
        float ls;
        const float* lb = g_part_l + (b * NSPLIT + s0) * NHEAD + h;
        if (g < NGRP - 1) {
            ls = 0.0f;
#pragma unroll
            for (int i = 0; i < 8; i++)
                ls += lb[i * NHEAD];
        } else {
            ls = lb[0];
        }
        g_l2[bh * NGRP + g] = ls;
    }
}

// ---------------------------------------------------------------------------
// Reduce stage B: sum 8 groups, normalize. grid = 128 (bh), block = 128 (d).
// ---------------------------------------------------------------------------
__global__ __launch_bounds__(128) void reduceB_kernel()
{
    const int bh = blockIdx.x;
    const int b = bh >> 3;
    const int h = bh & 7;
    const int d = threadIdx.x;

    float den = 0.0f;
#pragma unroll
    for (int g = 0; g < NGRP; g++)
        den += g_l2[bh * NGRP + g];

    float sum = 0.0f;
#pragma unroll
    for (int g = 0; g < NGRP; g++)
        sum += g_acc2[((long)bh * NGRP + g) * HDIM + d];

    g_attn[b * HID + h * HDIM + d] = sum * __frcp_rn(den);
}

// ---------------------------------------------------------------------------
// GEMM partials. grid = (8, KSPLIT), block = 128.
// ---------------------------------------------------------------------------
__global__ __launch_bounds__(128) void gemm_partial_kernel(const float* __restrict__ W)
{
    __shared__ float aS[BATCH][GEMM_KB];
    const int cb = blockIdx.x;
    const int kb = blockIdx.y;
    const int j = cb * 128 + threadIdx.x;
    const int k0 = kb * GEMM_KB;

    for (int e = threadIdx.x; e < BATCH * GEMM_KB; e += 128) {
        int bb = e / GEMM_KB;
        int kk = e % GEMM_KB;
        aS[bb][kk] = g_attn[bb * HID + k0 + kk];
    }
    __syncthreads();

    float accb[BATCH];
#pragma unroll
    for (int bb = 0; bb < BATCH; bb++) accb[bb] = 0.0f;

#pragma unroll 8
    for (int kk = 0; kk < GEMM_KB; kk++) {
        float w = W[(long)(k0 + kk) * HID + j];
#pragma unroll
        for (int bb = 0; bb < BATCH; bb++)
            accb[bb] = fmaf(aS[bb][kk], w, accb[bb]);
    }
#pragma unroll
    for (int bb = 0; bb < BATCH; bb++)
        g_gemm_part[(kb * BATCH + bb) * HID + j] = accb[bb];
}

// ---------------------------------------------------------------------------
// GEMM final sum (float4). grid = 32, block = 128.
// ---------------------------------------------------------------------------
__global__ __launch_bounds__(128) void gemm_final_kernel(float* __restrict__ out)
{
    const int idx = blockIdx.x * 128 + threadIdx.x;  // 4096 float4s
    float4 sum = make_float4(0.f, 0.f, 0.f, 0.f);
#pragma unroll
    for (int kb = 0; kb < KSPLIT; kb++) {
        float4 p = ldg4(g_gemm_part + (long)kb * BATCH * HID + idx * 4);
        sum.x += p.x; sum.y += p.y; sum.z += p.z; sum.w += p.w;
    }
    reinterpret_cast<float4*>(out)[idx] = sum;
}

// ---------------------------------------------------------------------------
extern "C" void kernel_launch(void* const* d_in, const int* in_sizes, int n_in,
                              void* d_out, int out_size)
{
    const float* q  = (const float*)d_in[0];
    const float* k  = (const float*)d_in[1];
    const float* v  = (const float*)d_in[2];
    const float* kc = (const float*)d_in[4];
    const float* vc = (const float*)d_in[5];
    const int* bt   = (const int*)d_in[6];
    const int* sl   = (const int*)d_in[7];
    const float* Wo = (const float*)d_in[8];
    float* out = (float*)d_out;

    setup_kernel<<<2048 + BATCH, 128>>>(bt, sl);
    score_kernel<<<dim3(NSPLIT, BATCH), 256>>>(q, k, kc);
    wv_kernel<<<dim3(NSPLIT, BATCH), 256>>>(v, vc);
    reduceA_kernel<<<dim3(NGRP, BATCH * NHEAD), 128>>>();
    reduceB_kernel<<<BATCH * NHEAD, 128>>>();
    gemm_partial_kernel<<<dim3(8, KSPLIT), 128>>>(Wo);
    gemm_final_kernel<<<32, 128>>>(out);
}

// round 16
// speedup vs baseline: 1.0845x; 1.0845x over previous
#include <cuda_runtime.h>
#include <math.h>

#define BATCH 16
#define NHEAD 8
#define HDIM 128
#define BSZ 16
#define SEQL 4096
#define MAXB 384
#define HID 1024
#define NTOK 4097          // 16 sink + 4064 window + 16 partial block + 1 new
#define NSPLIT 57          // ceil(4097 / 72); no empty splits
#define TPS 72             // MULTIPLE OF 8
#define NTOKP 4104         // row pitch (mult of 8, 16B-aligned)
#define NGRP 8             // reduce stage-A groups
#define KSPLIT 16
#define GEMM_KB 64
#define SCALE 0.08838834764831845f
#define MSHIFT 10.0f       // fixed softmax shift (scores bounded << 80)

typedef unsigned long long u64;

// ---------------- scratch (device globals: no allocation allowed) ----------
__device__ float g_part_acc[BATCH * NSPLIT * NHEAD * HDIM]; // 3.6 MB
__device__ float g_part_l[BATCH * NSPLIT * NHEAD];
__device__ float g_acc2[BATCH * NHEAD * NGRP * HDIM];
__device__ float g_l2[BATCH * NHEAD * NGRP];
__device__ float g_scores[BATCH * NHEAD * NTOKP];           // weights
__device__ float g_attn[BATCH * HID];
__device__ float g_gemm_part[KSPLIT * BATCH * HID];
__device__ float g_ropeT[SEQL * 128];   // per pos: [0:64) cos, [64:128) sin
__device__ float g_invf[64];
__device__ int2  g_rowpos[BATCH * NTOK];

__device__ __forceinline__ float4 ldg4(const float* p) {
    return *reinterpret_cast<const float4*>(p);
}
__device__ __forceinline__ ulonglong2 ldg4u(const float* p) {
    return *reinterpret_cast<const ulonglong2*>(p);
}
__device__ __forceinline__ u64 pk2(float a, float b) {
    u64 r; asm("mov.b64 %0, {%1, %2};" : "=l"(r) : "f"(a), "f"(b)); return r;
}
__device__ __forceinline__ u64 mul2(u64 a, u64 b) {
    u64 r; asm("mul.rn.f32x2 %0, %1, %2;" : "=l"(r) : "l"(a), "l"(b)); return r;
}
__device__ __forceinline__ u64 fma2(u64 a, u64 b, u64 c) {
    u64 r; asm("fma.rn.f32x2 %0, %1, %2, %3;" : "=l"(r) : "l"(a), "l"(b), "l"(c)); return r;
}
__device__ __forceinline__ float hadd2(u64 v) {
    float a, b; asm("mov.b64 {%0, %1}, %2;" : "=f"(a), "=f"(b) : "l"(v));
    return a + b;
}
__device__ __forceinline__ void cp_async16(void* smem, const void* gmem) {
    unsigned sa = (unsigned)__cvta_generic_to_shared(smem);
    asm volatile("cp.async.ca.shared.global [%0], [%1], 16;\n"
                 :: "r"(sa), "l"(gmem) : "memory");
}
__device__ __forceinline__ void cp_async_commit() {
    asm volatile("cp.async.commit_group;\n" ::: "memory");
}
__device__ __forceinline__ void cp_async_wait_all() {
    asm volatile("cp.async.wait_group 0;\n" ::: "memory");
}

// ---------------------------------------------------------------------------
// Setup 1: rowpos + (block 0) 64 inv-freqs via double pow (64 calls total).
// [R13 body, proven] grid = BATCH, block = 256.
// ---------------------------------------------------------------------------
__global__ __launch_bounds__(256) void rowpos_kernel(
    const int* __restrict__ bt, const int* __restrict__ sl)
{
    const int b = blockIdx.x;
    if (b == 0 && threadIdx.x < 64)
        g_invf[threadIdx.x] =
            (float)(1.0 / pow(10000.0, (double)threadIdx.x / 64.0));

    const int num_past = sl[b] - 1;
    const int mblk = num_past >> 4;
    const int rem = num_past & 15;
    const int* btb = bt + b * MAXB;

    for (int t = threadIdx.x; t < NTOK; t += 256) {
        int row, p;
        if (t < 16) {
            row = btb[0] * BSZ + t;
            p = t;
        } else if (t < 4080) {
            int blk = btb[mblk - 254 + ((t - 16) >> 4)];
            row = blk * BSZ + ((t - 16) & 15);
            p = t + 15 - rem;
        } else if (t < 4096) {
            int off = t - 4080;
            row = (off < rem) ? (btb[mblk] * BSZ + off) : -1;
            p = t - 1 - rem;
        } else {
            row = -2;
            p = 4095;
        }
        g_rowpos[b * NTOK + t] = make_int2(row, p);
    }
}

// ---------------------------------------------------------------------------
// Setup 2: RoPE cos/sin table (pure fp32 sincosf). grid=2048, block=128.
// ---------------------------------------------------------------------------
__global__ __launch_bounds__(128) void rope_table_kernel()
{
    const int idx = blockIdx.x * 128 + threadIdx.x;  // p*64 + f
    const int p = idx >> 6;
    const int f = idx & 63;
    float sv, cv;
    sincosf((float)p * g_invf[f], &sv, &cv);
    g_ropeT[p * 128 + f] = cv;
    g_ropeT[p * 128 + 64 + f] = sv;
}

// ---------------------------------------------------------------------------
// Kernel 1: weights w[b][h][t] = exp(dot(rope q, rope K_t)*SCALE - MSHIFT).
// grid = (NSPLIT, BATCH), block = 256 (warp == head).
// SINGLE-SHOT staging: all 72 tokens' cos/sin cp.async'd up front (36 KB),
// ONE wait + ONE barrier per split, then 9 barrier-free subgroups.
// Packed f32x2 math + transposed butterfly (proven R13 compute body).
// ---------------------------------------------------------------------------
__global__ __launch_bounds__(256) void score_kernel(
    const float* __restrict__ q, const float* __restrict__ k,
    const float* __restrict__ kc)
{
    __shared__ float sbuf[TPS][128];   // 36 KB
    __shared__ int srow[TPS];

    const int b = blockIdx.y;
    const int s = blockIdx.x;
    const int tid = threadIdx.x;
    const int h = tid >> 5;
    const int lane = tid & 31;
    const int A = lane & 15;
    const int half = lane >> 4;
    const int d4 = A * 4;
    const int tokoff = half * 4 + (A & 3);   // within an 8-token subgroup

    const int tstart = s * TPS;
    const int tend = min(tstart + TPS, NTOK);

    // ---- issue ALL staging loads first (9 cp.asyncs per thread) ----
#pragma unroll
    for (int e = tid; e < TPS * 32; e += 256) {
        const int ti = e >> 5;
        const int c = e & 31;
        const int t = tstart + ti;
        if (t < tend) {
            int2 rp = g_rowpos[b * NTOK + t];
            cp_async16(&sbuf[ti][c * 4], g_ropeT + rp.y * 128 + c * 4);
            if (c == 0) srow[ti] = rp.x;
        } else if (c == 0) {
            srow[ti] = -1;
        }
    }
    cp_async_commit();

    // ---- rope q at pos 4095 while staging flies ----
    const int hb = h * HDIM;
    float4 qx4 = ldg4(q + b * HID + hb + d4);
    float4 qy4 = ldg4(q + b * HID + hb + 64 + d4);
    float4 c04 = ldg4(g_ropeT + 4095 * 128 + d4);
    float4 s04 = ldg4(g_ropeT + 4095 * 128 + 64 + d4);
    float ql[4], qh[4];
    ql[0] = qx4.x * c04.x - qy4.x * s04.x;
    ql[1] = qx4.y * c04.y - qy4.y * s04.y;
    ql[2] = qx4.z * c04.z - qy4.z * s04.z;
    ql[3] = qx4.w * c04.w - qy4.w * s04.w;
    qh[0] = qy4.x * c04.x + qx4.x * s04.x;
    qh[1] = qy4.y * c04.y + qx4.y * s04.y;
    qh[2] = qy4.z * c04.z + qx4.z * s04.z;
    qh[3] = qy4.w * c04.w + qx4.w * s04.w;
    const u64 qlo0 = pk2(ql[0], ql[1]), qlo1 = pk2(ql[2], ql[3]);
    const u64 qhi0 = pk2(qh[0], qh[1]), qhi1 = pk2(qh[2], qh[3]);
    const u64 nqlo0 = pk2(-ql[0], -ql[1]), nqlo1 = pk2(-ql[2], -ql[3]);

    const float* kq = k + b * HID;
    const long sbase = (long)(b * NHEAD + h) * NTOKP;
    float lsum = 0.0f;

    // ---- single drain + barrier for the whole split ----
    cp_async_wait_all();
    __syncthreads();

    // ---- 9 subgroups of 8 tokens, no further barriers ----
#pragma unroll
    for (int goff = 0; goff < TPS; goff += 8) {
        if (tstart + goff >= tend) break;
        float dot[4];
#pragma unroll
        for (int sub = 0; sub < 4; sub++) {
            const int ti = goff + half * 4 + sub;
            const int row = srow[ti];
            const float* kp = (row == -2) ? kq : kc + (long)max(row, 0) * HID;
            ulonglong2 kx = ldg4u(kp + hb + d4);
            ulonglong2 ky = ldg4u(kp + hb + 64 + d4);
            ulonglong2 cc = *reinterpret_cast<const ulonglong2*>(&sbuf[ti][d4]);
            ulonglong2 ss = *reinterpret_cast<const ulonglong2*>(&sbuf[ti][64 + d4]);
            u64 acc = 0ULL;
            u64 P0 = fma2(qlo0, kx.x, mul2(qhi0, ky.x));
            u64 M0 = fma2(qhi0, kx.x, mul2(nqlo0, ky.x));
            acc = fma2(cc.x, P0, acc);
            acc = fma2(ss.x, M0, acc);
            u64 P1 = fma2(qlo1, kx.y, mul2(qhi1, ky.y));
            u64 M1 = fma2(qhi1, kx.y, mul2(nqlo1, ky.y));
            acc = fma2(cc.y, P1, acc);
            acc = fma2(ss.y, M1, acc);
            dot[sub] = hadd2(acc);
        }

        // ---- transposed butterfly over the 16-lane half ----
        float k0 = ((A & 1) == 0) ? dot[0] : dot[1];
        float s0 = ((A & 1) == 0) ? dot[1] : dot[0];
        float v01 = k0 + __shfl_xor_sync(0xffffffffu, s0, 1);
        float k1 = ((A & 1) == 0) ? dot[2] : dot[3];
        float s1 = ((A & 1) == 0) ? dot[3] : dot[2];
        float v23 = k1 + __shfl_xor_sync(0xffffffffu, s1, 1);
        float k2 = ((A & 2) == 0) ? v01 : v23;
        float s2 = ((A & 2) == 0) ? v23 : v01;
        float vv = k2 + __shfl_xor_sync(0xffffffffu, s2, 2);
        vv += __shfl_xor_sync(0xffffffffu, vv, 4);
        vv += __shfl_xor_sync(0xffffffffu, vv, 8);

        const int t_mine = tstart + goff + tokoff;
        const bool okm = (t_mine < tend) && (srow[goff + tokoff] != -1);
        float w = okm ? __expf(fmaf(vv, SCALE, -MSHIFT)) : 0.0f;
        if (A < 4) {
            g_scores[sbase + t_mine] = w;
            lsum += w;
        }
    }

    // warp-wide lsum (non-storing lanes hold 0)
#pragma unroll
    for (int o = 16; o > 0; o >>= 1)
        lsum += __shfl_xor_sync(0xffffffffu, lsum, o);
    if (lane == 0)
        g_part_l[(b * NSPLIT + s) * NHEAD + h] = lsum;
}

// ---------------------------------------------------------------------------
// Kernel 2: partials acc = sum_t w_t * V_t. Pure streaming (proven body).
// grid = (NSPLIT, BATCH), block = 256 (warp == head). No smem, no syncs.
// ---------------------------------------------------------------------------
__global__ __launch_bounds__(256) void wv_kernel(
    const float* __restrict__ v, const float* __restrict__ vc)
{
    const int b = blockIdx.y;
    const int s = blockIdx.x;
    const int tid = threadIdx.x;
    const int h = tid >> 5;
    const int lane = tid & 31;
    const int hoff = h * HDIM + lane * 4;

    const int tstart = s * TPS;
    const int tend = min(tstart + TPS, NTOK);
    const float* vq = v + b * HID;
    const float* wrow = g_scores + (long)(b * NHEAD + h) * NTOKP;

    float acc[4] = {0.f, 0.f, 0.f, 0.f};

    for (int t0 = tstart; t0 < tend; t0 += 8) {
        float4 w0 = ldg4(wrow + t0);
        float4 w1 = ldg4(wrow + t0 + 4);
        float wv_[8] = {w0.x, w0.y, w0.z, w0.w, w1.x, w1.y, w1.z, w1.w};
        float4 vv[8];
#pragma unroll
        for (int i = 0; i < 8; i++) {
            int t = min(t0 + i, NTOK - 1);
            int row = g_rowpos[b * NTOK + t].x;
            const float* vp = (row == -2) ? vq : vc + (long)max(row, 0) * HID;
            vv[i] = ldg4(vp + hoff);
        }
#pragma unroll
        for (int j = 0; j < 4; j++) {
            float x = acc[j];
#pragma unroll
            for (int i = 0; i < 8; i++)
                x = fmaf(wv_[i], (&vv[i].x)[j], x);
            acc[j] = x;
        }
    }

    float* pa = g_part_acc +
        (long)((b * NSPLIT + s) * NHEAD + h) * HDIM + lane * 4;
    pa[0] = acc[0]; pa[1] = acc[1]; pa[2] = acc[2]; pa[3] = acc[3];
}

// ---------------------------------------------------------------------------
// Reduce stage A: sum 8 splits per group (group 7 = split 56 only).
// grid = (NGRP, 128 bh), block = 128.
// ---------------------------------------------------------------------------
__global__ __launch_bounds__(128) void reduceA_kernel()
{
    const int g = blockIdx.x;
    const int bh = blockIdx.y;
    const int b = bh >> 3;
    const int h = bh & 7;
    const int d = threadIdx.x;
    const int s0 = g * 8;

    const float* base =
        g_part_acc + (long)((b * NSPLIT + s0) * NHEAD + h) * HDIM + d;
    float sum;
    if (g < NGRP - 1) {
        sum = 0.0f;
#pragma unroll
        for (int i = 0; i < 8; i++)
            sum += base[(long)i * NHEAD * HDIM];
    } else {
        sum = base[0];   // split 56 only
    }
    g_acc2[((long)bh * NGRP + g) * HDIM + d] = sum;

    if (d == 0) {
        float ls;
        const float* lb = g_part_l + (b * NSPLIT + s0) * NHEAD + h;
        if (g < NGRP - 1) {
            ls = 0.0f;
#pragma unroll
            for (int i = 0; i < 8; i++)
                ls += lb[i * NHEAD];
        } else {
            ls = lb[0];
        }
        g_l2[bh * NGRP + g] = ls;
    }
}

// ---------------------------------------------------------------------------
// Reduce stage B: sum 8 groups, normalize. grid = 128 (bh), block = 128 (d).
// ---------------------------------------------------------------------------
__global__ __launch_bounds__(128) void reduceB_kernel()
{
    const int bh = blockIdx.x;
    const int b = bh >> 3;
    const int h = bh & 7;
    const int d = threadIdx.x;

    float den = 0.0f;
#pragma unroll
    for (int g = 0; g < NGRP; g++)
        den += g_l2[bh * NGRP + g];

    float sum = 0.0f;
#pragma unroll
    for (int g = 0; g < NGRP; g++)
        sum += g_acc2[((long)bh * NGRP + g) * HDIM + d];

    g_attn[b * HID + h * HDIM + d] = sum * __frcp_rn(den);
}

// ---------------------------------------------------------------------------
// GEMM partials. grid = (8, KSPLIT), block = 128.
// ---------------------------------------------------------------------------
__global__ __launch_bounds__(128) void gemm_partial_kernel(const float* __restrict__ W)
{
    __shared__ float aS[BATCH][GEMM_KB];
    const int cb = blockIdx.x;
    const int kb = blockIdx.y;
    const int j = cb * 128 + threadIdx.x;
    const int k0 = kb * GEMM_KB;

    for (int e = threadIdx.x; e < BATCH * GEMM_KB; e += 128) {
        int bb = e / GEMM_KB;
        int kk = e % GEMM_KB;
        aS[bb][kk] = g_attn[bb * HID + k0 + kk];
    }
    __syncthreads();

    float accb[BATCH];
#pragma unroll
    for (int bb = 0; bb < BATCH; bb++) accb[bb] = 0.0f;

#pragma unroll 8
    for (int kk = 0; kk < GEMM_KB; kk++) {
        float w = W[(long)(k0 + kk) * HID + j];
#pragma unroll
        for (int bb = 0; bb < BATCH; bb++)
            accb[bb] = fmaf(aS[bb][kk], w, accb[bb]);
    }
#pragma unroll
    for (int bb = 0; bb < BATCH; bb++)
        g_gemm_part[(kb * BATCH + bb) * HID + j] = accb[bb];
}

// ---------------------------------------------------------------------------
// GEMM final sum (float4). grid = 32, block = 128.
// ---------------------------------------------------------------------------
__global__ __launch_bounds__(128) void gemm_final_kernel(float* __restrict__ out)
{
    const int idx = blockIdx.x * 128 + threadIdx.x;  // 4096 float4s
    float4 sum = make_float4(0.f, 0.f, 0.f, 0.f);
#pragma unroll
    for (int kb = 0; kb < KSPLIT; kb++) {
        float4 p = ldg4(g_gemm_part + (long)kb * BATCH * HID + idx * 4);
        sum.x += p.x; sum.y += p.y; sum.z += p.z; sum.w += p.w;
    }
    reinterpret_cast<float4*>(out)[idx] = sum;
}

// ---------------------------------------------------------------------------
extern "C" void kernel_launch(void* const* d_in, const int* in_sizes, int n_in,
                              void* d_out, int out_size)
{
    const float* q  = (const float*)d_in[0];
    const float* k  = (const float*)d_in[1];
    const float* v  = (const float*)d_in[2];
    const float* kc = (const float*)d_in[4];
    const float* vc = (const float*)d_in[5];
    const int* bt   = (const int*)d_in[6];
    const int* sl   = (const int*)d_in[7];
    const float* Wo = (const float*)d_in[8];
    float* out = (float*)d_out;

    rowpos_kernel<<<BATCH, 256>>>(bt, sl);
    rope_table_kernel<<<2048, 128>>>();
    score_kernel<<<dim3(NSPLIT, BATCH), 256>>>(q, k, kc);
    wv_kernel<<<dim3(NSPLIT, BATCH), 256>>>(v, vc);
    reduceA_kernel<<<dim3(NGRP, BATCH * NHEAD), 128>>>();
    reduceB_kernel<<<BATCH * NHEAD, 128>>>();
    gemm_partial_kernel<<<dim3(8, KSPLIT), 128>>>(Wo);
    gemm_final_kernel<<<32, 128>>>(out);
}